// round 2
// baseline (speedup 1.0000x reference)
#include <cuda_runtime.h>
#include <cstdint>
#include <cstddef>

// NF4-dequant fused SGEMM:  out[m,n] = sum_k x[m,k] * (NF4[codes[n,k]] * absmax[n,k/64]) + bias[n]
// M = B*S = 4096, N = 4096, K = 4096 for this problem (derived from in_sizes at launch).
//
// 128x128x16 tiled, double-buffered SMEM, 8x8 register tile per thread,
// inner product via packed fp32 FFMA2 (fma.rn.f32x2) — the only way to reach
// full fp32 rate on Blackwell (3-reg FFMA is half-rate, rt_SMSP=2 vs 1).

#define BM 128
#define BN 128
#define BK 16
#define TM 8
#define TN 8
#define NTHREADS 256
#define PITCH (BM + 4)   // pad so transposed stores hit distinct banks; 132 floats

__constant__ float NF4_CODE[16] = {
    -1.0f, -0.6961928009986877f, -0.5250730514526367f, -0.39491748809814453f,
    -0.28444138169288635f, -0.18477343022823334f, -0.09105003625154495f, 0.0f,
    0.07958029955625534f, 0.16093020141124725f, 0.24611230194568634f,
    0.33791524171829224f, 0.44070982933044434f, 0.5626170039176941f,
    0.6797559261322021f, 1.0f};

__device__ __forceinline__ uint64_t pack2(float lo, float hi) {
    uint64_t r;
    asm("mov.b64 %0, {%1, %2};" : "=l"(r) : "f"(lo), "f"(hi));
    return r;
}

__device__ __forceinline__ void unpack2(uint64_t v, float& lo, float& hi) {
    asm("mov.b64 {%0, %1}, %2;" : "=f"(lo), "=f"(hi) : "l"(v));
}

// packed 2xfp32 fma: acc = a * b + acc  (sm_100-family instruction)
__device__ __forceinline__ void ffma2(uint64_t& acc, uint64_t a, uint64_t b) {
    asm("fma.rn.f32x2 %0, %1, %2, %0;" : "+l"(acc) : "l"(a), "l"(b));
}

__global__ __launch_bounds__(NTHREADS, 1)
void nf4_gemm_kernel(const float* __restrict__ x,
                     const int* __restrict__ codes,
                     const float* __restrict__ absmax,
                     const float* __restrict__ bias,
                     float* __restrict__ out,
                     int M, int N, int K) {
    __shared__ float As[2][BK][PITCH];   // As[buf][k][m]
    __shared__ float Ws[2][BK][PITCH];   // Ws[buf][k][n]
    __shared__ float lut[16];

    const int t  = threadIdx.x;
    const int m0 = blockIdx.y * BM;
    const int n0 = blockIdx.x * BN;
    const int tx = t & 15;               // 16 thread-cols * TN = 128
    const int ty = t >> 4;               // 16 thread-rows * TM = 128
    const int kb = K >> 6;               // absmax columns (K / 64)

    if (t < 16) lut[t] = NF4_CODE[t];

    uint64_t acc[TM][TN / 2];
    #pragma unroll
    for (int i = 0; i < TM; i++)
        #pragma unroll
        for (int j = 0; j < TN / 2; j++)
            acc[i][j] = 0ull;            // two packed +0.0f

    const int NT = K / BK;

    // ---- preload tile 0 into buffer 0 ----
    __syncthreads();                     // lut visible before dequant below
    {
        const int k0 = 0;
        #pragma unroll
        for (int l = 0; l < 2; l++) {
            int idx = t + l * NTHREADS;  // 0..511
            int row = idx >> 2;          // 0..127
            int kc  = idx & 3;           // float4 column within BK
            float4 av = *(const float4*)(x + (size_t)(m0 + row) * K + k0 + kc * 4);
            As[0][kc * 4 + 0][row] = av.x;
            As[0][kc * 4 + 1][row] = av.y;
            As[0][kc * 4 + 2][row] = av.z;
            As[0][kc * 4 + 3][row] = av.w;
            int4 cv = *(const int4*)(codes + (size_t)(n0 + row) * K + k0 + kc * 4);
            float sc = absmax[(size_t)(n0 + row) * kb + (k0 >> 6)];
            Ws[0][kc * 4 + 0][row] = lut[cv.x] * sc;
            Ws[0][kc * 4 + 1][row] = lut[cv.y] * sc;
            Ws[0][kc * 4 + 2][row] = lut[cv.z] * sc;
            Ws[0][kc * 4 + 3][row] = lut[cv.w] * sc;
        }
    }
    __syncthreads();

    for (int kt = 0; kt < NT; kt++) {
        const int buf = kt & 1;
        const bool has_next = (kt + 1 < NT);

        // ---- prefetch next tile into registers ----
        float4 pa[2];
        int4   pw[2];
        float  psc[2];
        if (has_next) {
            const int k0 = (kt + 1) * BK;
            #pragma unroll
            for (int l = 0; l < 2; l++) {
                int idx = t + l * NTHREADS;
                int row = idx >> 2;
                int kc  = idx & 3;
                pa[l]  = *(const float4*)(x + (size_t)(m0 + row) * K + k0 + kc * 4);
                pw[l]  = *(const int4*)(codes + (size_t)(n0 + row) * K + k0 + kc * 4);
                psc[l] = absmax[(size_t)(n0 + row) * kb + (k0 >> 6)];
            }
        }

        // ---- compute on current buffer ----
        #pragma unroll
        for (int kk = 0; kk < BK; kk++) {
            uint64_t a2[TM];
            #pragma unroll
            for (int i = 0; i < TM; i++) {
                float a = As[buf][kk][ty * TM + i];
                a2[i] = pack2(a, a);
            }
            float4 b0 = *(const float4*)&Ws[buf][kk][tx * TN];
            float4 b1 = *(const float4*)&Ws[buf][kk][tx * TN + 4];
            uint64_t b2[TN / 2];
            b2[0] = pack2(b0.x, b0.y);
            b2[1] = pack2(b0.z, b0.w);
            b2[2] = pack2(b1.x, b1.y);
            b2[3] = pack2(b1.z, b1.w);
            #pragma unroll
            for (int i = 0; i < TM; i++)
                #pragma unroll
                for (int jp = 0; jp < TN / 2; jp++)
                    ffma2(acc[i][jp], a2[i], b2[jp]);
        }

        // ---- stage prefetched tile into other buffer ----
        if (has_next) {
            const int nb = buf ^ 1;
            #pragma unroll
            for (int l = 0; l < 2; l++) {
                int idx = t + l * NTHREADS;
                int row = idx >> 2;
                int kc  = idx & 3;
                As[nb][kc * 4 + 0][row] = pa[l].x;
                As[nb][kc * 4 + 1][row] = pa[l].y;
                As[nb][kc * 4 + 2][row] = pa[l].z;
                As[nb][kc * 4 + 3][row] = pa[l].w;
                float sc = psc[l];
                Ws[nb][kc * 4 + 0][row] = lut[pw[l].x] * sc;
                Ws[nb][kc * 4 + 1][row] = lut[pw[l].y] * sc;
                Ws[nb][kc * 4 + 2][row] = lut[pw[l].z] * sc;
                Ws[nb][kc * 4 + 3][row] = lut[pw[l].w] * sc;
            }
        }
        __syncthreads();
    }

    // ---- epilogue: + bias, nan/inf -> 0, store ----
    const int ncol = n0 + tx * TN;
    float bv[TN];
    #pragma unroll
    for (int j = 0; j < TN; j++) bv[j] = bias[ncol + j];

    #pragma unroll
    for (int i = 0; i < TM; i++) {
        int m = m0 + ty * TM + i;
        float v[TN];
        #pragma unroll
        for (int jp = 0; jp < TN / 2; jp++)
            unpack2(acc[i][jp], v[2 * jp], v[2 * jp + 1]);
        #pragma unroll
        for (int j = 0; j < TN; j++) {
            float r = v[j] + bv[j];
            // branchless nan_to_num(nan=0, posinf=0, neginf=0)
            bool bad = (__float_as_uint(r) & 0x7f800000u) == 0x7f800000u;
            v[j] = bad ? 0.0f : r;
        }
        float4* o = (float4*)(out + (size_t)m * N + ncol);
        o[0] = make_float4(v[0], v[1], v[2], v[3]);
        o[1] = make_float4(v[4], v[5], v[6], v[7]);
    }
}

extern "C" void kernel_launch(void* const* d_in, const int* in_sizes, int n_in,
                              void* d_out, int out_size) {
    const float* x      = (const float*)d_in[0];
    const int*   codes  = (const int*)d_in[1];
    const float* absmax = (const float*)d_in[2];
    const float* bias   = (const float*)d_in[3];
    float*       out    = (float*)d_out;

    const int N = in_sizes[3];                                   // OUT
    const int K = (int)(((long long)in_sizes[2] * 64) / N);      // IN
    const int M = in_sizes[0] / K;                               // B*S

    dim3 grid(N / BN, M / BM);
    nf4_gemm_kernel<<<grid, NTHREADS>>>(x, codes, absmax, bias, out, M, N, K);
}

// round 6
// speedup vs baseline: 3.4304x; 3.4304x over previous
#include <cuda_runtime.h>
#include <cstdint>
#include <cstddef>

// NF4-dequant fused GEMM via mma.sync tf32 (legacy tensor-core path — the
// harness compiles at plain sm_100, where tcgen05 is unavailable).
// out[m,n] = sum_k x[m,k] * (NF4[codes[n,k]] * absmax[n,k/64]) + bias[n]
//
// CTA tile 128x128x32, double-buffered SMEM (XOR-swizzled 128B rows).
// 8 warps (2x4), warp tile 64x32. Fragments fed with ldmatrix.m8n8.b16
// (an 8x8 b16 matrix == an 8x4 b32/tf32 fragment with the exact
// m16n8k8 thread mapping). W stored [n][k] == B col-major fragment.

#define BM 128
#define BN 128
#define BK 32
#define THREADS 256
#define ASZ (BM * BK * 4)               // 16 KB per A stage
#define WSZ (BN * BK * 4)               // 16 KB per W stage
#define SMEM_LUT 0
#define SMEM_TILES 1024
#define SMEM_TOTAL (SMEM_TILES + 2 * (ASZ + WSZ))   // 66560 B

__constant__ float NF4_CODE[16] = {
    -1.0f, -0.6961928009986877f, -0.5250730514526367f, -0.39491748809814453f,
    -0.28444138169288635f, -0.18477343022823334f, -0.09105003625154495f, 0.0f,
    0.07958029955625534f, 0.16093020141124725f, 0.24611230194568634f,
    0.33791524171829224f, 0.44070982933044434f, 0.5626170039176941f,
    0.6797559261322021f, 1.0f};

// ---------- helpers ----------
__device__ __forceinline__ uint32_t smem_u32(const void* p) {
    uint32_t a;
    asm("{ .reg .u64 t; cvta.to.shared.u64 t, %1; cvt.u32.u64 %0, t; }"
        : "=r"(a) : "l"(p));
    return a;
}

__device__ __forceinline__ uint32_t f2tf32(float f) {
    uint32_t r;
    asm("cvt.rn.tf32.f32 %0, %1;" : "=r"(r) : "f"(f));
    return r;
}

__device__ __forceinline__ float lds_f32(uint32_t addr) {
    float v;
    asm volatile("ld.shared.f32 %0, [%1];" : "=f"(v) : "r"(addr));
    return v;
}

__device__ __forceinline__ void sts128(uint32_t addr, uint32_t a, uint32_t b,
                                       uint32_t c, uint32_t d) {
    asm volatile("st.shared.v4.b32 [%0], {%1, %2, %3, %4};"
                 :: "r"(addr), "r"(a), "r"(b), "r"(c), "r"(d) : "memory");
}

__device__ __forceinline__ void ldsm4(uint32_t* d, uint32_t addr) {
    asm volatile("ldmatrix.sync.aligned.m8n8.x4.shared.b16 {%0,%1,%2,%3}, [%4];"
                 : "=r"(d[0]), "=r"(d[1]), "=r"(d[2]), "=r"(d[3]) : "r"(addr));
}

__device__ __forceinline__ void mma_tf32(float* c, const uint32_t* a,
                                         uint32_t b0, uint32_t b1) {
    asm volatile(
        "mma.sync.aligned.m16n8k8.row.col.f32.tf32.tf32.f32 "
        "{%0,%1,%2,%3}, {%4,%5,%6,%7}, {%8,%9}, {%0,%1,%2,%3};"
        : "+f"(c[0]), "+f"(c[1]), "+f"(c[2]), "+f"(c[3])
        : "r"(a[0]), "r"(a[1]), "r"(a[2]), "r"(a[3]), "r"(b0), "r"(b1));
}

// swizzled byte offset for (row, chunk16B) inside a [rows][BK] f32 tile
__device__ __forceinline__ uint32_t sw_off(uint32_t row, uint32_t chunk) {
    return row * (BK * 4) + ((chunk ^ (row & 7)) << 4);
}

// ---------- kernel ----------
__global__ __launch_bounds__(THREADS)
void nf4_mma_kernel(const float* __restrict__ x,
                    const int* __restrict__ codes,
                    const float* __restrict__ absmax,
                    const float* __restrict__ bias,
                    float* __restrict__ out,
                    int M, int N, int K) {
    extern __shared__ char smem[];
    const uint32_t sb = smem_u32(smem);

    const int t    = threadIdx.x;
    const int lane = t & 31;
    const int wid  = t >> 5;
    const int m0   = blockIdx.y * BM;
    const int n0   = blockIdx.x * BN;
    const int kb   = K >> 6;

    const uint32_t sA[2] = {sb + SMEM_TILES,            sb + SMEM_TILES + ASZ + WSZ};
    const uint32_t sW[2] = {sb + SMEM_TILES + ASZ,      sb + SMEM_TILES + 2*ASZ + WSZ};

    if (t < 16) *(float*)(smem + SMEM_LUT + t * 4) = NF4_CODE[t];
    __syncthreads();

    // warp position: 2 warps along M (64 rows), 4 along N (32 cols)
    const int wm = (wid & 1) * 64;
    const int wn = (wid >> 1) * 32;

    // ldmatrix lane geometry (identical formula for A and B fragments)
    const int g     = lane >> 3;                    // octet 0..3
    const int r_loc = (lane & 7) + ((g & 1) << 3);  // 0..15
    const int chalf = g >> 1;                       // 0/1 -> +4 k cols

    // staging geometry: idx = t + l*256 -> row = idx>>3 (0..127), chunk = idx&7
    const int srow = t >> 3;        // base row, +32 per l
    const int schk = t & 7;         // 16B chunk within the 32-float row

    float acc[4][4][4];             // [mt][nt][frag]
    #pragma unroll
    for (int i = 0; i < 4; i++)
        #pragma unroll
        for (int j = 0; j < 4; j++)
            #pragma unroll
            for (int f = 0; f < 4; f++) acc[i][j][f] = 0.0f;

    const int NITER = K / BK;
    const uint32_t lut = sb + SMEM_LUT;

    // ---- preload tile 0 into stage 0 ----
    #pragma unroll
    for (int l = 0; l < 4; l++) {
        int row = srow + l * 32;
        float4 av = *(const float4*)(x + (size_t)(m0 + row) * K + schk * 4);
        int4   cv = *(const int4*)(codes + (size_t)(n0 + row) * K + schk * 4);
        float  sc = __ldg(absmax + (size_t)(n0 + row) * kb);
        uint32_t o = sw_off(row, schk);
        sts128(sA[0] + o, f2tf32(av.x), f2tf32(av.y), f2tf32(av.z), f2tf32(av.w));
        float w0 = lds_f32(lut + ((cv.x & 15) << 2)) * sc;
        float w1 = lds_f32(lut + ((cv.y & 15) << 2)) * sc;
        float w2 = lds_f32(lut + ((cv.z & 15) << 2)) * sc;
        float w3 = lds_f32(lut + ((cv.w & 15) << 2)) * sc;
        sts128(sW[0] + o, f2tf32(w0), f2tf32(w1), f2tf32(w2), f2tf32(w3));
    }
    __syncthreads();

    #pragma unroll 1
    for (int it = 0; it < NITER; it++) {
        const int s = it & 1;
        const bool has_next = (it + 1 < NITER);

        // ---- prefetch next K-chunk into registers ----
        float4 av[4]; int4 cv[4]; float sc[4];
        if (has_next) {
            const int k0 = (it + 1) * BK;
            #pragma unroll
            for (int l = 0; l < 4; l++) {
                int row = srow + l * 32;
                av[l] = *(const float4*)(x + (size_t)(m0 + row) * K + k0 + schk * 4);
                cv[l] = *(const int4*)(codes + (size_t)(n0 + row) * K + k0 + schk * 4);
                sc[l] = __ldg(absmax + (size_t)(n0 + row) * kb + (k0 >> 6));
            }
        }

        // ---- compute on stage s: 4 k8 steps ----
        #pragma unroll
        for (int ks = 0; ks < 4; ks++) {
            const uint32_t chunk = (uint32_t)(ks * 2 + chalf);

            // B fragments: 2 LDSM.x4 cover 4 n-tiles
            uint32_t bf[2][4];
            #pragma unroll
            for (int p = 0; p < 2; p++) {
                uint32_t row = (uint32_t)(wn + p * 16 + r_loc);
                ldsm4(bf[p], sW[s] + sw_off(row, chunk));
            }
            // A fragments + MMAs per m-tile
            #pragma unroll
            for (int mt = 0; mt < 4; mt++) {
                uint32_t row = (uint32_t)(wm + mt * 16 + r_loc);
                uint32_t af[4];
                ldsm4(af, sA[s] + sw_off(row, chunk));
                #pragma unroll
                for (int nt = 0; nt < 4; nt++) {
                    const uint32_t* b = bf[nt >> 1];
                    // matrix order: {b0_t0, b0_t1, b1_t0, b1_t1}
                    mma_tf32(acc[mt][nt], af, b[nt & 1], b[2 + (nt & 1)]);
                }
            }
        }

        // ---- stage prefetched chunk into the other buffer ----
        if (has_next) {
            const int ns = s ^ 1;
            #pragma unroll
            for (int l = 0; l < 4; l++) {
                int row = srow + l * 32;
                uint32_t o = sw_off(row, schk);
                sts128(sA[ns] + o, f2tf32(av[l].x), f2tf32(av[l].y),
                                   f2tf32(av[l].z), f2tf32(av[l].w));
                float w0 = lds_f32(lut + ((cv[l].x & 15) << 2)) * sc[l];
                float w1 = lds_f32(lut + ((cv[l].y & 15) << 2)) * sc[l];
                float w2 = lds_f32(lut + ((cv[l].z & 15) << 2)) * sc[l];
                float w3 = lds_f32(lut + ((cv[l].w & 15) << 2)) * sc[l];
                sts128(sW[ns] + o, f2tf32(w0), f2tf32(w1), f2tf32(w2), f2tf32(w3));
            }
        }
        __syncthreads();
    }

    // ---- epilogue ----
    const int qr = lane >> 2;          // 0..7
    const int qc = (lane & 3) << 1;    // 0,2,4,6

    #pragma unroll
    for (int nt = 0; nt < 4; nt++) {
        const int n = n0 + wn + nt * 8 + qc;
        const float b0 = __ldg(bias + n);
        const float b1 = __ldg(bias + n + 1);
        #pragma unroll
        for (int mt = 0; mt < 4; mt++) {
            const int mrow = m0 + wm + mt * 16 + qr;
            float v0 = acc[mt][nt][0] + b0;
            float v1 = acc[mt][nt][1] + b1;
            float v2 = acc[mt][nt][2] + b0;
            float v3 = acc[mt][nt][3] + b1;
            v0 = ((__float_as_uint(v0) & 0x7f800000u) == 0x7f800000u) ? 0.0f : v0;
            v1 = ((__float_as_uint(v1) & 0x7f800000u) == 0x7f800000u) ? 0.0f : v1;
            v2 = ((__float_as_uint(v2) & 0x7f800000u) == 0x7f800000u) ? 0.0f : v2;
            v3 = ((__float_as_uint(v3) & 0x7f800000u) == 0x7f800000u) ? 0.0f : v3;
            *(float2*)(out + (size_t)mrow * N + n)       = make_float2(v0, v1);
            *(float2*)(out + (size_t)(mrow + 8) * N + n) = make_float2(v2, v3);
        }
    }
}

extern "C" void kernel_launch(void* const* d_in, const int* in_sizes, int n_in,
                              void* d_out, int out_size) {
    const float* x      = (const float*)d_in[0];
    const int*   codes  = (const int*)d_in[1];
    const float* absmax = (const float*)d_in[2];
    const float* bias   = (const float*)d_in[3];
    float*       out    = (float*)d_out;

    const int N = in_sizes[3];                                   // OUT
    const int K = (int)(((long long)in_sizes[2] * 64) / N);      // IN
    const int M = in_sizes[0] / K;                               // B*S

    cudaFuncSetAttribute(nf4_mma_kernel,
                         cudaFuncAttributeMaxDynamicSharedMemorySize, SMEM_TOTAL);

    dim3 grid(N / BN, M / BM);
    nf4_mma_kernel<<<grid, THREADS, SMEM_TOTAL>>>(x, codes, absmax, bias, out, M, N, K);
}

// round 8
// speedup vs baseline: 4.0179x; 1.1712x over previous
#include <cuda_runtime.h>
#include <cstdint>
#include <cstddef>

// NF4-dequant GEMM, round 7: two prep kernels pre-convert x -> tf32 and
// dequantize codes -> tf32 W into __device__ scratch; the GEMM mainloop is
// a pure cp.async 3-stage pipeline feeding mma.sync.m16n8k8.tf32 with
// ldmatrix.b16 (8x8 b16 == 8x4 b32 fragment). CTA 128x256x32, warp 64x64.

#define BM 128
#define BN 256
#define BK 32
#define THREADS 256
#define STAGES 3
#define ASZ (BM * BK * 4)                 // 16 KB
#define WSZ (BN * BK * 4)                 // 32 KB
#define STAGE_STRIDE (ASZ + WSZ)          // 48 KB
#define SMEM_TOTAL (STAGES * STAGE_STRIDE)

#define MAX_ELEMS (4096 * 4096)
__device__ float g_xs[MAX_ELEMS];         // x pre-converted to tf32 bits
__device__ float g_wt[MAX_ELEMS];         // W dequantized to tf32 bits

__constant__ float NF4_CODE[16] = {
    -1.0f, -0.6961928009986877f, -0.5250730514526367f, -0.39491748809814453f,
    -0.28444138169288635f, -0.18477343022823334f, -0.09105003625154495f, 0.0f,
    0.07958029955625534f, 0.16093020141124725f, 0.24611230194568634f,
    0.33791524171829224f, 0.44070982933044434f, 0.5626170039176941f,
    0.6797559261322021f, 1.0f};

// ---------- helpers ----------
__device__ __forceinline__ uint32_t smem_u32(const void* p) {
    uint32_t a;
    asm("{ .reg .u64 t; cvta.to.shared.u64 t, %1; cvt.u32.u64 %0, t; }"
        : "=r"(a) : "l"(p));
    return a;
}

__device__ __forceinline__ uint32_t f2tf32(float f) {
    uint32_t r;
    asm("cvt.rn.tf32.f32 %0, %1;" : "=r"(r) : "f"(f));
    return r;
}

__device__ __forceinline__ void cp16(uint32_t saddr, const void* gptr) {
    asm volatile("cp.async.cg.shared.global [%0], [%1], 16;"
                 :: "r"(saddr), "l"(gptr) : "memory");
}

__device__ __forceinline__ void cp_commit() {
    asm volatile("cp.async.commit_group;" ::: "memory");
}

template <int N>
__device__ __forceinline__ void cp_wait() {
    asm volatile("cp.async.wait_group %0;" :: "n"(N) : "memory");
}

__device__ __forceinline__ void ldsm4(uint32_t* d, uint32_t addr) {
    asm volatile("ldmatrix.sync.aligned.m8n8.x4.shared.b16 {%0,%1,%2,%3}, [%4];"
                 : "=r"(d[0]), "=r"(d[1]), "=r"(d[2]), "=r"(d[3]) : "r"(addr));
}

__device__ __forceinline__ void mma_tf32(float* c, const uint32_t* a,
                                         uint32_t b0, uint32_t b1) {
    asm volatile(
        "mma.sync.aligned.m16n8k8.row.col.f32.tf32.tf32.f32 "
        "{%0,%1,%2,%3}, {%4,%5,%6,%7}, {%8,%9}, {%0,%1,%2,%3};"
        : "+f"(c[0]), "+f"(c[1]), "+f"(c[2]), "+f"(c[3])
        : "r"(a[0]), "r"(a[1]), "r"(a[2]), "r"(a[3]), "r"(b0), "r"(b1));
}

// swizzled byte offset for (row, chunk16B) inside a [rows][BK] f32 tile
__device__ __forceinline__ uint32_t sw_off(uint32_t row, uint32_t chunk) {
    return row * (BK * 4) + ((chunk ^ (row & 7)) << 4);
}

// ---------- prep kernels ----------
__global__ __launch_bounds__(256)
void prep_x_kernel(const float* __restrict__ x, int n4) {
    int stride = gridDim.x * blockDim.x;
    for (int i = blockIdx.x * blockDim.x + threadIdx.x; i < n4; i += stride) {
        float4 v = ((const float4*)x)[i];
        uint4 o;
        o.x = f2tf32(v.x); o.y = f2tf32(v.y);
        o.z = f2tf32(v.z); o.w = f2tf32(v.w);
        ((uint4*)g_xs)[i] = o;
    }
}

__global__ __launch_bounds__(256)
void prep_w_kernel(const int* __restrict__ codes,
                   const float* __restrict__ absmax, int n4, int K) {
    int stride = gridDim.x * blockDim.x;
    const int kb = K >> 6;
    for (int i = blockIdx.x * blockDim.x + threadIdx.x; i < n4; i += stride) {
        int4 c = ((const int4*)codes)[i];
        int e = i << 2;                    // first element index
        int n = e / K, k = e - n * K;      // 4 consecutive k share one block
        float sc = __ldg(absmax + (size_t)n * kb + (k >> 6));
        uint4 o;
        o.x = f2tf32(NF4_CODE[c.x & 15] * sc);
        o.y = f2tf32(NF4_CODE[c.y & 15] * sc);
        o.z = f2tf32(NF4_CODE[c.z & 15] * sc);
        o.w = f2tf32(NF4_CODE[c.w & 15] * sc);
        ((uint4*)g_wt)[i] = o;
    }
}

// ---------- GEMM kernel ----------
__global__ __launch_bounds__(THREADS)
void nf4_mma2_kernel(const float* __restrict__ bias,
                     float* __restrict__ out,
                     int M, int N, int K) {
    extern __shared__ char smem[];
    const uint32_t sb = smem_u32(smem);

    const int t    = threadIdx.x;
    const int lane = t & 31;
    const int wid  = t >> 5;
    const int m0   = blockIdx.y * BM;
    const int n0   = blockIdx.x * BN;

    // warp position: 2 warps along M (64), 4 along N (64)
    const int wm = (wid & 1) * 64;
    const int wn = (wid >> 1) * 64;

    // ldmatrix lane geometry (same formula for A and B fragments)
    const int g     = lane >> 3;
    const int r_loc = (lane & 7) + ((g & 1) << 3);
    const int chalf = g >> 1;

    // staging geometry
    const int srow = t >> 3;              // base row (0..31), +32 per chunk-batch
    const int schk = t & 7;               // 16B chunk in 128B row

    // per-thread gmem byte pointers (k0 added at issue time)
    const char* aBase[4];
    const char* wBase[8];
    #pragma unroll
    for (int l = 0; l < 4; l++)
        aBase[l] = (const char*)(g_xs + (size_t)(m0 + srow + l * 32) * K + schk * 4);
    #pragma unroll
    for (int l = 0; l < 8; l++)
        wBase[l] = (const char*)(g_wt + (size_t)(n0 + srow + l * 32) * K + schk * 4);

    uint32_t swA[4], swW[8];
    #pragma unroll
    for (int l = 0; l < 4; l++) swA[l] = sw_off(srow + l * 32, schk);
    #pragma unroll
    for (int l = 0; l < 8; l++) swW[l] = sw_off(srow + l * 32, schk);

    float acc[4][8][4];
    #pragma unroll
    for (int i = 0; i < 4; i++)
        #pragma unroll
        for (int j = 0; j < 8; j++)
            #pragma unroll
            for (int f = 0; f < 4; f++) acc[i][j][f] = 0.0f;

    const int NITER = K / BK;

    // issue stage 'st' into buffer st%STAGES
    auto issue = [&](int st) {
        const uint32_t bufA = sb + (st % STAGES) * STAGE_STRIDE;
        const uint32_t bufW = bufA + ASZ;
        const size_t kOff = (size_t)(st * BK) * 4;
        #pragma unroll
        for (int l = 0; l < 4; l++) cp16(bufA + swA[l], aBase[l] + kOff);
        #pragma unroll
        for (int l = 0; l < 8; l++) cp16(bufW + swW[l], wBase[l] + kOff);
        cp_commit();
    };

    issue(0);
    issue(1);

    #pragma unroll 1
    for (int it = 0; it < NITER; it++) {
        if (it + 1 < NITER) cp_wait<1>(); else cp_wait<0>();
        __syncthreads();

        const uint32_t bufA = sb + (it % STAGES) * STAGE_STRIDE;
        const uint32_t bufW = bufA + ASZ;

        #pragma unroll
        for (int ks = 0; ks < 4; ks++) {
            const uint32_t chunk = (uint32_t)(ks * 2 + chalf);
            uint32_t bf[4][4];
            #pragma unroll
            for (int p = 0; p < 4; p++)
                ldsm4(bf[p], bufW + sw_off((uint32_t)(wn + p * 16 + r_loc), chunk));
            #pragma unroll
            for (int mt = 0; mt < 4; mt++) {
                uint32_t af[4];
                ldsm4(af, bufA + sw_off((uint32_t)(wm + mt * 16 + r_loc), chunk));
                #pragma unroll
                for (int nt = 0; nt < 8; nt++) {
                    const uint32_t* b = bf[nt >> 1];
                    mma_tf32(acc[mt][nt], af, b[nt & 1], b[2 + (nt & 1)]);
                }
            }
        }
        __syncthreads();

        if (it + 2 < NITER) issue(it + 2);
    }

    // ---- epilogue ----
    const int qr = lane >> 2;
    const int qc = (lane & 3) << 1;

    #pragma unroll
    for (int nt = 0; nt < 8; nt++) {
        const int n = n0 + wn + nt * 8 + qc;
        const float b0 = __ldg(bias + n);
        const float b1 = __ldg(bias + n + 1);
        #pragma unroll
        for (int mt = 0; mt < 4; mt++) {
            const int mrow = m0 + wm + mt * 16 + qr;
            float v0 = acc[mt][nt][0] + b0;
            float v1 = acc[mt][nt][1] + b1;
            float v2 = acc[mt][nt][2] + b0;
            float v3 = acc[mt][nt][3] + b1;
            v0 = ((__float_as_uint(v0) & 0x7f800000u) == 0x7f800000u) ? 0.0f : v0;
            v1 = ((__float_as_uint(v1) & 0x7f800000u) == 0x7f800000u) ? 0.0f : v1;
            v2 = ((__float_as_uint(v2) & 0x7f800000u) == 0x7f800000u) ? 0.0f : v2;
            v3 = ((__float_as_uint(v3) & 0x7f800000u) == 0x7f800000u) ? 0.0f : v3;
            *(float2*)(out + (size_t)mrow * N + n)       = make_float2(v0, v1);
            *(float2*)(out + (size_t)(mrow + 8) * N + n) = make_float2(v2, v3);
        }
    }
}

extern "C" void kernel_launch(void* const* d_in, const int* in_sizes, int n_in,
                              void* d_out, int out_size) {
    const float* x      = (const float*)d_in[0];
    const int*   codes  = (const int*)d_in[1];
    const float* absmax = (const float*)d_in[2];
    const float* bias   = (const float*)d_in[3];
    float*       out    = (float*)d_out;

    const int N = in_sizes[3];                                   // OUT
    const int K = (int)(((long long)in_sizes[2] * 64) / N);      // IN
    const int M = in_sizes[0] / K;                               // B*S

    prep_x_kernel<<<4096, 256>>>(x, in_sizes[0] / 4);
    prep_w_kernel<<<4096, 256>>>(codes, absmax, in_sizes[1] / 4, K);

    cudaFuncSetAttribute(nf4_mma2_kernel,
                         cudaFuncAttributeMaxDynamicSharedMemorySize, SMEM_TOTAL);
    dim3 grid(N / BN, M / BM);
    nf4_mma2_kernel<<<grid, THREADS, SMEM_TOTAL>>>(bias, out, M, N, K);
}

// round 11
// speedup vs baseline: 4.7629x; 1.1854x over previous
#include <cuda_runtime.h>
#include <cstdint>
#include <cstddef>

// NF4-dequant GEMM, round 9/10: prep kernels (x->tf32, W dequant->tf32 in
// __device__ scratch) + cp.async 3-stage pipelined mma.sync tf32 GEMM.
// CTA 128x128x32, warp tile 64x32, __launch_bounds__(256,2) -> 2 CTAs/SM
// (the R8 64x64-warp-tile config needed >128 regs and pinned occupancy to
// 1 CTA/SM; issue-slot starvation, not smem traffic, was the binder).

#define BM 128
#define BN 128
#define BK 32
#define THREADS 256
#define STAGES 3
#define ASZ (BM * BK * 4)                 // 16 KB
#define WSZ (BN * BK * 4)                 // 16 KB
#define STAGE_STRIDE (ASZ + WSZ)          // 32 KB
#define SMEM_TOTAL (STAGES * STAGE_STRIDE) // 96 KB

#define MAX_ELEMS (4096 * 4096)
__device__ float g_xs[MAX_ELEMS];         // x pre-converted to tf32 bits
__device__ float g_wt[MAX_ELEMS];         // W dequantized to tf32 bits

__constant__ float NF4_CODE[16] = {
    -1.0f, -0.6961928009986877f, -0.5250730514526367f, -0.39491748809814453f,
    -0.28444138169288635f, -0.18477343022823334f, -0.09105003625154495f, 0.0f,
    0.07958029955625534f, 0.16093020141124725f, 0.24611230194568634f,
    0.33791524171829224f, 0.44070982933044434f, 0.5626170039176941f,
    0.6797559261322021f, 1.0f};

// ---------- helpers ----------
__device__ __forceinline__ uint32_t smem_u32(const void* p) {
    uint32_t a;
    asm("{ .reg .u64 t; cvta.to.shared.u64 t, %1; cvt.u32.u64 %0, t; }"
        : "=r"(a) : "l"(p));
    return a;
}

__device__ __forceinline__ uint32_t f2tf32(float f) {
    uint32_t r;
    asm("cvt.rn.tf32.f32 %0, %1;" : "=r"(r) : "f"(f));
    return r;
}

__device__ __forceinline__ void cp16(uint32_t saddr, const void* gptr) {
    asm volatile("cp.async.cg.shared.global [%0], [%1], 16;"
                 :: "r"(saddr), "l"(gptr) : "memory");
}

__device__ __forceinline__ void cp_commit() {
    asm volatile("cp.async.commit_group;" ::: "memory");
}

template <int N>
__device__ __forceinline__ void cp_wait() {
    asm volatile("cp.async.wait_group %0;" :: "n"(N) : "memory");
}

__device__ __forceinline__ void ldsm4(uint32_t* d, uint32_t addr) {
    asm volatile("ldmatrix.sync.aligned.m8n8.x4.shared.b16 {%0,%1,%2,%3}, [%4];"
                 : "=r"(d[0]), "=r"(d[1]), "=r"(d[2]), "=r"(d[3]) : "r"(addr));
}

__device__ __forceinline__ void mma_tf32(float* c, const uint32_t* a,
                                         uint32_t b0, uint32_t b1) {
    asm volatile(
        "mma.sync.aligned.m16n8k8.row.col.f32.tf32.tf32.f32 "
        "{%0,%1,%2,%3}, {%4,%5,%6,%7}, {%8,%9}, {%0,%1,%2,%3};"
        : "+f"(c[0]), "+f"(c[1]), "+f"(c[2]), "+f"(c[3])
        : "r"(a[0]), "r"(a[1]), "r"(a[2]), "r"(a[3]), "r"(b0), "r"(b1));
}

// swizzled byte offset for (row, chunk16B) inside a [rows][BK] f32 tile
__device__ __forceinline__ uint32_t sw_off(uint32_t row, uint32_t chunk) {
    return row * (BK * 4) + ((chunk ^ (row & 7)) << 4);
}

// ---------- prep kernels ----------
__global__ __launch_bounds__(256)
void prep_x_kernel(const float* __restrict__ x, int n4) {
    int stride = gridDim.x * blockDim.x;
    for (int i = blockIdx.x * blockDim.x + threadIdx.x; i < n4; i += stride) {
        float4 v = ((const float4*)x)[i];
        uint4 o;
        o.x = f2tf32(v.x); o.y = f2tf32(v.y);
        o.z = f2tf32(v.z); o.w = f2tf32(v.w);
        ((uint4*)g_xs)[i] = o;
    }
}

__global__ __launch_bounds__(256)
void prep_w_kernel(const int* __restrict__ codes,
                   const float* __restrict__ absmax, int n4, int K) {
    int stride = gridDim.x * blockDim.x;
    const int kb = K >> 6;
    for (int i = blockIdx.x * blockDim.x + threadIdx.x; i < n4; i += stride) {
        int4 c = ((const int4*)codes)[i];
        int e = i << 2;
        int n = e / K, k = e - n * K;
        float sc = __ldg(absmax + (size_t)n * kb + (k >> 6));
        uint4 o;
        o.x = f2tf32(NF4_CODE[c.x & 15] * sc);
        o.y = f2tf32(NF4_CODE[c.y & 15] * sc);
        o.z = f2tf32(NF4_CODE[c.z & 15] * sc);
        o.w = f2tf32(NF4_CODE[c.w & 15] * sc);
        ((uint4*)g_wt)[i] = o;
    }
}

// ---------- GEMM kernel ----------
__global__ __launch_bounds__(THREADS, 2)
void nf4_mma3_kernel(const float* __restrict__ bias,
                     float* __restrict__ out,
                     int M, int N, int K) {
    extern __shared__ char smem[];
    const uint32_t sb = smem_u32(smem);

    const int t    = threadIdx.x;
    const int lane = t & 31;
    const int wid  = t >> 5;
    const int m0   = blockIdx.y * BM;
    const int n0   = blockIdx.x * BN;

    // warp position: 2 warps along M (64), 4 along N (32)
    const int wm = (wid & 1) * 64;
    const int wn = (wid >> 1) * 32;

    // ldmatrix lane geometry (same for A and B fragments)
    const int g     = lane >> 3;
    const int r_loc = (lane & 7) + ((g & 1) << 3);
    const int chalf = g >> 1;

    // staging geometry: 8 threads per 128B row
    const int srow = t >> 3;              // 0..31, +32 per l
    const int schk = t & 7;

    const char* aBase[4];
    const char* wBase[4];
    #pragma unroll
    for (int l = 0; l < 4; l++) {
        aBase[l] = (const char*)(g_xs + (size_t)(m0 + srow + l * 32) * K + schk * 4);
        wBase[l] = (const char*)(g_wt + (size_t)(n0 + srow + l * 32) * K + schk * 4);
    }
    uint32_t swS[4];
    #pragma unroll
    for (int l = 0; l < 4; l++) swS[l] = sw_off(srow + l * 32, schk);

    float acc[4][4][4];
    #pragma unroll
    for (int i = 0; i < 4; i++)
        #pragma unroll
        for (int j = 0; j < 4; j++)
            #pragma unroll
            for (int f = 0; f < 4; f++) acc[i][j][f] = 0.0f;

    const int NITER = K / BK;

    auto issue = [&](int st) {
        const uint32_t bufA = sb + (st % STAGES) * STAGE_STRIDE;
        const uint32_t bufW = bufA + ASZ;
        const size_t kOff = (size_t)(st * BK) * 4;
        #pragma unroll
        for (int l = 0; l < 4; l++) cp16(bufA + swS[l], aBase[l] + kOff);
        #pragma unroll
        for (int l = 0; l < 4; l++) cp16(bufW + swS[l], wBase[l] + kOff);
        cp_commit();
    };

    issue(0);
    issue(1);

    #pragma unroll 1
    for (int it = 0; it < NITER; it++) {
        if (it + 1 < NITER) cp_wait<1>(); else cp_wait<0>();
        __syncthreads();
        // safe: buffer (it+2)%3 == (it-1)%3, fully consumed once every warp
        // passed the barrier above (they all finished compute of it-1).
        if (it + 2 < NITER) issue(it + 2);

        const uint32_t bufA = sb + (it % STAGES) * STAGE_STRIDE;
        const uint32_t bufW = bufA + ASZ;

        #pragma unroll
        for (int ks = 0; ks < 4; ks++) {
            const uint32_t chunk = (uint32_t)(ks * 2 + chalf);
            uint32_t bf[2][4];
            #pragma unroll
            for (int p = 0; p < 2; p++)
                ldsm4(bf[p], bufW + sw_off((uint32_t)(wn + p * 16 + r_loc), chunk));
            #pragma unroll
            for (int mt = 0; mt < 4; mt++) {
                uint32_t af[4];
                ldsm4(af, bufA + sw_off((uint32_t)(wm + mt * 16 + r_loc), chunk));
                #pragma unroll
                for (int nt = 0; nt < 4; nt++) {
                    const uint32_t* b = bf[nt >> 1];
                    mma_tf32(acc[mt][nt], af, b[nt & 1], b[2 + (nt & 1)]);
                }
            }
        }
    }

    // ---- epilogue ----
    const int qr = lane >> 2;
    const int qc = (lane & 3) << 1;

    #pragma unroll
    for (int nt = 0; nt < 4; nt++) {
        const int n = n0 + wn + nt * 8 + qc;
        const float b0 = __ldg(bias + n);
        const float b1 = __ldg(bias + n + 1);
        #pragma unroll
        for (int mt = 0; mt < 4; mt++) {
            const int mrow = m0 + wm + mt * 16 + qr;
            float v0 = acc[mt][nt][0] + b0;
            float v1 = acc[mt][nt][1] + b1;
            float v2 = acc[mt][nt][2] + b0;
            float v3 = acc[mt][nt][3] + b1;
            v0 = ((__float_as_uint(v0) & 0x7f800000u) == 0x7f800000u) ? 0.0f : v0;
            v1 = ((__float_as_uint(v1) & 0x7f800000u) == 0x7f800000u) ? 0.0f : v1;
            v2 = ((__float_as_uint(v2) & 0x7f800000u) == 0x7f800000u) ? 0.0f : v2;
            v3 = ((__float_as_uint(v3) & 0x7f800000u) == 0x7f800000u) ? 0.0f : v3;
            *(float2*)(out + (size_t)mrow * N + n)       = make_float2(v0, v1);
            *(float2*)(out + (size_t)(mrow + 8) * N + n) = make_float2(v2, v3);
        }
    }
}

extern "C" void kernel_launch(void* const* d_in, const int* in_sizes, int n_in,
                              void* d_out, int out_size) {
    const float* x      = (const float*)d_in[0];
    const int*   codes  = (const int*)d_in[1];
    const float* absmax = (const float*)d_in[2];
    const float* bias   = (const float*)d_in[3];
    float*       out    = (float*)d_out;

    const int N = in_sizes[3];                                   // OUT
    const int K = (int)(((long long)in_sizes[2] * 64) / N);      // IN
    const int M = in_sizes[0] / K;                               // B*S

    prep_x_kernel<<<4096, 256>>>(x, in_sizes[0] / 4);
    prep_w_kernel<<<4096, 256>>>(codes, absmax, in_sizes[1] / 4, K);

    cudaFuncSetAttribute(nf4_mma3_kernel,
                         cudaFuncAttributeMaxDynamicSharedMemorySize, SMEM_TOTAL);
    dim3 grid(N / BN, M / BM);
    nf4_mma3_kernel<<<grid, THREADS, SMEM_TOTAL>>>(bias, out, M, N, K);
}